// round 11
// baseline (speedup 1.0000x reference)
#include <cuda_runtime.h>
#include <cstdint>
#include <cstddef>

#define SQ 4096
#define NB 64
#define HH 256
#define GC 1024   // 4 gates * 256 units, packed: pcol = j*4 + e  (e: 0=f,1=i,2=o,3=c)

typedef unsigned long long ull;

// ---------------- static device scratch (no allocations allowed) ----------------
__device__ float g_xg[(size_t)SQ * NB * GC];   // 1 GB input projections (+bias)
__device__ float g_Wp[HH * GC];                // packed W_all [k][pcol]
__device__ float g_Up[HH * GC];                // packed U_all [k][pcol]
__device__ float g_bp[GC];                     // packed bias
__device__ float g_hT[NB * HH];                // final hidden state
__device__ ull g_mb[2][16][HH][4];             // mailbox: duplicated h pairs [buf][grp][k][b], 256KB
__device__ unsigned g_bar[16];                 // per-group monotonic counters

// ---------------- f32x2 + memory helpers ----------------
__device__ __forceinline__ ull pk2(float x, float y) {
    ull r; asm("mov.b64 %0, {%1, %2};" : "=l"(r) : "f"(x), "f"(y)); return r;
}
__device__ __forceinline__ void fma2(ull& d, ull a, ull b) {
    asm("fma.rn.f32x2 %0, %1, %2, %0;" : "+l"(d) : "l"(a), "l"(b));
}
__device__ __forceinline__ float2 unpk(ull v) {
    float2 r; asm("mov.b64 {%0, %1}, %2;" : "=f"(r.x), "=f"(r.y) : "l"(v)); return r;
}
union F4U2 { float4 f4; ulonglong2 u2; };

__device__ __forceinline__ unsigned ldacq(const unsigned* p) {
    unsigned v; asm volatile("ld.acquire.gpu.global.u32 %0, [%1];" : "=r"(v) : "l"(p) : "memory"); return v;
}
__device__ __forceinline__ void strel64(ull* p, ull v) {
    asm volatile("st.relaxed.gpu.global.u64 [%0], %1;" :: "l"(p), "l"(v) : "memory");
}
__device__ __forceinline__ void redrel(unsigned* p) {
    asm volatile("red.release.gpu.global.add.u32 [%0], 1;" :: "l"(p) : "memory");
}
__device__ __forceinline__ float fsig(float x) { return 1.0f / (1.0f + __expf(-x)); }
__device__ __forceinline__ float ftanh(float x) { return 1.0f - 2.0f / (__expf(2.0f * x) + 1.0f); }

// ---------------- phase 0: pack weights + init mailbox/counters ----------------
__global__ void pack_kernel(const float* __restrict__ Wf, const float* __restrict__ Uf, const float* __restrict__ bf,
                            const float* __restrict__ Wi, const float* __restrict__ Ui, const float* __restrict__ bi,
                            const float* __restrict__ Wc, const float* __restrict__ Uc, const float* __restrict__ bc,
                            const float* __restrict__ Wo, const float* __restrict__ Uo, const float* __restrict__ bo)
{
    int i = blockIdx.x * blockDim.x + threadIdx.x;   // 0 .. 262143
    if (i < HH * GC) {
        int k = i >> 10, p = i & 1023;
        int j = p >> 2, e = p & 3;                   // e: 0=f,1=i,2=o,3=c
        const float* W = (e == 0) ? Wf : (e == 1) ? Wi : (e == 2) ? Wo : Wc;
        const float* U = (e == 0) ? Uf : (e == 1) ? Ui : (e == 2) ? Uo : Uc;
        g_Wp[i] = W[k * HH + j];
        g_Up[i] = U[k * HH + j];
        if (k == 0) {
            const float* B = (e == 0) ? bf : (e == 1) ? bi : (e == 2) ? bo : bc;
            g_bp[p] = B[j];
        }
    }
    if (i < 16 * HH * 4) ((ull*)g_mb)[i] = 0ull;    // buffer 0 = zeros (step-0 h)
    if (i < 16) g_bar[i] = 0u;                      // counters reset every launch
}

// ---------------- phase 1: xg[s*64+b][pcol] = x[b][s][:] @ Wp + bias ----------------
__global__ __launch_bounds__(256) void xproj_kernel(const float* __restrict__ x)
{
    __shared__ float As[8][132];   // [k][m], padded
    __shared__ float Bs[8][128];   // [k][n]
    int t  = threadIdx.x;
    int m0 = blockIdx.x * 128;
    int n0 = blockIdx.y * 128;
    int tm = t >> 4, tn = t & 15;

    int arow = t >> 1;
    int akq  = (t & 1) * 4;
    int gm = m0 + arow;
    int bb = gm & 63, ss = gm >> 6;
    const float* aptr = x + ((size_t)bb * SQ + ss) * HH + akq;

    int bkk = t >> 5;
    int bnq = (t & 31) * 4;
    const float* bptr = g_Wp + (size_t)bkk * GC + n0 + bnq;

    ull acc[8][4];
#pragma unroll
    for (int i = 0; i < 8; i++)
#pragma unroll
        for (int j = 0; j < 4; j++) acc[i][j] = 0ull;

    for (int k0 = 0; k0 < HH; k0 += 8) {
        float4 av = *(const float4*)(aptr + k0);
        float4 bv = *(const float4*)(bptr + (size_t)k0 * GC);
        __syncthreads();
        As[akq + 0][arow] = av.x;
        As[akq + 1][arow] = av.y;
        As[akq + 2][arow] = av.z;
        As[akq + 3][arow] = av.w;
        *(float4*)&Bs[bkk][bnq] = bv;
        __syncthreads();
#pragma unroll
        for (int kk = 0; kk < 8; kk++) {
            F4U2 b0, b1;
            float4 a0 = *(const float4*)&As[kk][tm * 8];
            float4 a1 = *(const float4*)&As[kk][tm * 8 + 4];
            b0.f4 = *(const float4*)&Bs[kk][tn * 8];
            b1.f4 = *(const float4*)&Bs[kk][tn * 8 + 4];
            ull bp_[4] = { b0.u2.x, b0.u2.y, b1.u2.x, b1.u2.y };
            float aa[8] = { a0.x, a0.y, a0.z, a0.w, a1.x, a1.y, a1.z, a1.w };
#pragma unroll
            for (int i = 0; i < 8; i++) {
                ull ad = pk2(aa[i], aa[i]);
#pragma unroll
                for (int j = 0; j < 4; j++) fma2(acc[i][j], ad, bp_[j]);
            }
        }
    }

    float4 bi0 = *(const float4*)(g_bp + n0 + tn * 8);
    float4 bi1 = *(const float4*)(g_bp + n0 + tn * 8 + 4);
#pragma unroll
    for (int i = 0; i < 8; i++) {
        float2 v0 = unpk(acc[i][0]), v1 = unpk(acc[i][1]);
        float2 v2 = unpk(acc[i][2]), v3 = unpk(acc[i][3]);
        float* o = g_xg + (size_t)(m0 + tm * 8 + i) * GC + n0 + tn * 8;
        float4 w0 = { v0.x + bi0.x, v0.y + bi0.y, v1.x + bi0.z, v1.y + bi0.w };
        float4 w1 = { v2.x + bi1.x, v2.y + bi1.y, v3.x + bi1.z, v3.y + bi1.w };
        *(float4*)o = w0;
        *(float4*)(o + 4) = w1;
    }
}

// ---------------- phase 2: persistent recurrence (R3 topology, de-fatted) ----------------
// 128 CTAs = 16 groups (4 batches) x 8 col-CTAs (128 gate-cols = 32 units).
// Sync: t0 acquire-polls group counter; publish = st.relaxed + bar + t0 red.release.
// U: kk 0-15 of each k-split in registers, kk 16-31 in 64KB smU.
__global__ __launch_bounds__(256, 1) void rnn_kernel()
{
    extern __shared__ float smU[];          // [8 ks][16 rows][128 cols] = 64KB used (112KB reserved)
    __shared__ ull  smH[HH * 4];            // duplicated pairs [k*4 + b], 8KB
    __shared__ float smR[8][4][128];        // [ksplit][batch][col] partials, 16KB

    int t   = threadIdx.x;
    int grp = blockIdx.x >> 3;
    int r   = blockIdx.x & 7;
    int c0  = r * 128;

    int ks = t >> 5, cg = t & 31;           // GEMM map: k-split, col-quad
    int eb = t >> 5, ecq = t & 31;          // epilogue map (t<128): batch, unit-quad
    int unit = r * 32 + ecq;

    // smU rows kk=16..31 of each split
    for (int q = t; q < 128 * 32; q += 256) {
        int row = q >> 5, cq4 = q & 31;
        int ks2 = row >> 4, j = row & 15;
        int kg = ks2 * 32 + 16 + j;
        ((float4*)smU)[q] = *(const float4*)(g_Up + (size_t)kg * GC + c0 + cq4 * 4);
    }
    // register rows kk=0..15 (pre-packed col pairs)
    ull ur0[16], ur1[16];
#pragma unroll
    for (int kk = 0; kk < 16; kk++) {
        F4U2 v; v.f4 = __ldg((const float4*)(g_Up + (size_t)(ks * 32 + kk) * GC + c0 + 4 * cg));
        ur0[kk] = v.u2.x;
        ur1[kk] = v.u2.y;
    }
    __syncthreads();

    const unsigned* barp = &g_bar[grp];
    float C = 0.0f;

    for (int s = 0; s < SQ; s++) {
        // xg prefetch before blocking (hides DRAM behind the poll)
        float4 xg4;
        if (t < 128)
            xg4 = __ldcs((const float4*)(g_xg + ((size_t)s * NB + grp * 4 + eb) * GC + c0 + 4 * ecq));

        if (s > 0 && t == 0) {
            unsigned tgt = 8u * (unsigned)s;
            while (ldacq(barp) < tgt) { }
        }
        __syncthreads();                                        // B1: h(s) globally ready

        // stage h slice: thread t = k index, 32B coalesced, already duplicated
        {
            const ulonglong2* src = (const ulonglong2*)&g_mb[s & 1][grp][t][0];
            ulonglong2 va = __ldcg(src);
            ulonglong2 vb = __ldcg(src + 1);
            *(ulonglong2*)&smH[t * 4]     = va;
            *(ulonglong2*)&smH[t * 4 + 2] = vb;
        }
        __syncthreads();                                        // B2: smH staged

        // GEMM partials: g[b][cols] += sum_{k in split} h[b][k] * U[k][cols]
        ull a00 = 0, a01 = 0, a10 = 0, a11 = 0, a20 = 0, a21 = 0, a30 = 0, a31 = 0;
        int kb = ks * 32;
#pragma unroll
        for (int kk = 0; kk < 16; kk++) {
            ulonglong2 hA = *(const ulonglong2*)&smH[(kb + kk) * 4];
            ulonglong2 hB = *(const ulonglong2*)&smH[(kb + kk) * 4 + 2];
            fma2(a00, hA.x, ur0[kk]); fma2(a01, hA.x, ur1[kk]);
            fma2(a10, hA.y, ur0[kk]); fma2(a11, hA.y, ur1[kk]);
            fma2(a20, hB.x, ur0[kk]); fma2(a21, hB.x, ur1[kk]);
            fma2(a30, hB.y, ur0[kk]); fma2(a31, hB.y, ur1[kk]);
        }
#pragma unroll
        for (int kk = 0; kk < 16; kk++) {
            int k = kb + 16 + kk;
            F4U2 u; u.f4 = *(const float4*)&smU[(ks * 16 + kk) * 128 + 4 * cg];
            ulonglong2 hA = *(const ulonglong2*)&smH[k * 4];
            ulonglong2 hB = *(const ulonglong2*)&smH[k * 4 + 2];
            fma2(a00, hA.x, u.u2.x); fma2(a01, hA.x, u.u2.y);
            fma2(a10, hA.y, u.u2.x); fma2(a11, hA.y, u.u2.y);
            fma2(a20, hB.x, u.u2.x); fma2(a21, hB.x, u.u2.y);
            fma2(a30, hB.y, u.u2.x); fma2(a31, hB.y, u.u2.y);
        }
        {
            float2 x0 = unpk(a00), x1 = unpk(a01);
            *(float4*)&smR[ks][0][4 * cg] = make_float4(x0.x, x0.y, x1.x, x1.y);
            x0 = unpk(a10); x1 = unpk(a11);
            *(float4*)&smR[ks][1][4 * cg] = make_float4(x0.x, x0.y, x1.x, x1.y);
            x0 = unpk(a20); x1 = unpk(a21);
            *(float4*)&smR[ks][2][4 * cg] = make_float4(x0.x, x0.y, x1.x, x1.y);
            x0 = unpk(a30); x1 = unpk(a31);
            *(float4*)&smR[ks][3][4 * cg] = make_float4(x0.x, x0.y, x1.x, x1.y);
        }
        __syncthreads();                                        // B3: partials ready

        // reduce + gates + state + publish (no per-thread fence)
        if (t < 128) {
            float4 g4 = xg4;
#pragma unroll
            for (int q = 0; q < 8; q++) {
                float4 pv = *(const float4*)&smR[q][eb][4 * ecq];
                g4.x += pv.x; g4.y += pv.y; g4.z += pv.z; g4.w += pv.w;
            }
            float fg = fsig(g4.x), ig = fsig(g4.y), og = fsig(g4.z), cc = fsig(g4.w);
            C = fg * C + ig * cc;
            float h = og * ftanh(C);

            if (s < SQ - 1) {
                strel64(&g_mb[(s + 1) & 1][grp][unit][eb], pk2(h, h));
            } else {
                g_hT[(grp * 4 + eb) * HH + unit] = h;
            }
        }
        __syncthreads();                                        // B4: all publishes issued
        if (t == 0) redrel(&g_bar[grp]);   // release after bar: covers all threads' stores
    }
}

// ---------------- phase 3: out = h_T @ Why + bias_y ----------------
__global__ __launch_bounds__(256) void out_kernel(const float* __restrict__ Why,
                                                  const float* __restrict__ by,
                                                  float* __restrict__ out)
{
    __shared__ float hs[HH];
    int b = blockIdx.x, n = threadIdx.x;
    hs[n] = g_hT[b * HH + n];
    __syncthreads();
    float acc = by[n];
    for (int k = 0; k < HH; k++)
        acc = fmaf(hs[k], Why[(size_t)k * HH + n], acc);
    out[b * HH + n] = acc;
}

// ---------------- launch ----------------
extern "C" void kernel_launch(void* const* d_in, const int* in_sizes, int n_in,
                              void* d_out, int out_size)
{
    (void)in_sizes; (void)n_in; (void)out_size;
    const float* x   = (const float*)d_in[0];
    const float* Wf  = (const float*)d_in[1];
    const float* Uf  = (const float*)d_in[2];
    const float* bf  = (const float*)d_in[3];
    const float* Wi  = (const float*)d_in[4];
    const float* Ui  = (const float*)d_in[5];
    const float* bi  = (const float*)d_in[6];
    const float* Wc  = (const float*)d_in[7];
    const float* Uc  = (const float*)d_in[8];
    const float* bc  = (const float*)d_in[9];
    const float* Wo  = (const float*)d_in[10];
    const float* Uo  = (const float*)d_in[11];
    const float* bo  = (const float*)d_in[12];
    const float* Why = (const float*)d_in[13];
    const float* by  = (const float*)d_in[14];
    float* out = (float*)d_out;

    pack_kernel<<<1024, 256>>>(Wf, Uf, bf, Wi, Ui, bi, Wc, Uc, bc, Wo, Uo, bo);

    dim3 g1(2048, 8);
    xproj_kernel<<<g1, 256>>>(x);

    // 112KB dynamic (64KB used) forces 1 CTA/SM -> all 128 CTAs co-resident
    int smem = 112 * 1024;
    cudaFuncSetAttribute(rnn_kernel, cudaFuncAttributeMaxDynamicSharedMemorySize, smem);
    rnn_kernel<<<128, 256, smem>>>();

    out_kernel<<<64, 256>>>(Why, by, out);
}